// round 7
// baseline (speedup 1.0000x reference)
#include <cuda_runtime.h>
#include <cuda_bf16.h>

#define PP     76800     // H*W
#define HH     240
#define WW     320
#define NC     22        // classes
#define NG     6         // u64 groups of 4 u16 class lanes (24 >= 22)
#define RPAD   24        // u8 histogram row stride (6 words)
#define NQ     300       // query points (15*20)
#define QW     20        // queries per row
#define QSKIP  16
#define EPSF   1e-6f
#define C1F    (0.9f * 1e-6f)

#define THR    640       // threads per block
#define BLKS   120       // blocks (2 image rows each); < 148 SMs => co-resident

// ---------------- device scratch (zero-init; reset by last block each launch) -
__device__ unsigned long long g_accP[NQ * NG];  // votes: 4 u16 class lanes / u64
__device__ int                g_clsCnt[NC];
__device__ float              g_zsum[NC];
__device__ int                g_phase1;
__device__ int                g_phase2;

// ---------------- shared inlier test (identical rounding in vote & zsum) -----
// Equivalent (in reals) to  (cx*ux+cy*uy)/(sqrt(cx^2+cy^2)+eps) > 0.9
__device__ __forceinline__ bool itest(float cx, float cy, float ux, float uy) {
    float rhs = fmaf(cx * cx, 0.81f, (0.81f * cy) * cy);
    float t   = fmaf(cx, ux, fmaf(cy, uy, -C1F));
    return t * fabsf(t) > rhs;
}

// =============== single persistent kernel: prep + vote + reduce + final ======
__global__ void __launch_bounds__(THR) k_all(const int* __restrict__ label,
                                             const float* __restrict__ vp,
                                             const float* __restrict__ extents,
                                             const float* __restrict__ poses,
                                             const float* __restrict__ mdata,
                                             float* __restrict__ out) {
    __shared__ union {
        unsigned char      cnt[4 * NQ * RPAD];   // phase 1: 28.8 KB histograms
        unsigned long long tab[NQ * NG];         // phase 2: 14.4 KB vote table
    } sB;
    __shared__ float4       sU4[2 * (WW / 2)];   // (ux,uy) pairs, 2 rows, 5.1 KB
    __shared__ unsigned int sLab2[2 * (WW / 2)]; // u16 label pairs, 1.3 KB
    __shared__ float        sDz[2 * WW];         // 2.5 KB
    __shared__ float sZ[NC];
    __shared__ int   sCC[NC];
    __shared__ int   sBQ[NC];
    __shared__ float sBV[NC];
    __shared__ int   sLast;

    int t    = threadIdx.x;
    int lane = t & 31;
    int blk  = blockIdx.x;

    // zero histograms
    #pragma unroll
    for (int i = t; i < 4 * NQ * RPAD / 4; i += THR)
        reinterpret_cast<unsigned int*>(sB.cnt)[i] = 0u;
    if (t < NC) { sZ[t] = 0.0f; sCC[t] = 0; }
    if (t == 0) sLast = 0;

    // ---------------- prep: one pixel per thread (2 rows = 640 px) -----------
    {
        int p   = blk * (2 * WW) + t;
        int lab = label[p];
        float ux = 0.0f, uy = 0.0f, dz = 0.0f;
        if (lab > 0) {
            float dx = vp[(3 * lab + 0) * PP + p];
            float dy = vp[(3 * lab + 1) * PP + p];
            dz       = vp[(3 * lab + 2) * PP + p];
            float dn = sqrtf(dx * dx + dy * dy) + EPSF;
            ux = dx / dn;
            uy = dy / dn;
        }
        reinterpret_cast<float2*>(sU4)[t]           = make_float2(ux, uy);
        reinterpret_cast<unsigned short*>(sLab2)[t] = (unsigned short)lab;
        sDz[t] = dz;
        unsigned m = __match_any_sync(0xffffffffu, lab);
        if (lane == __ffs(m) - 1) atomicAdd(&sCC[lab], __popc(m));
    }
    __syncthreads();

    // ---------------- vote: 2 copies of 300 queries, each scans 160 px x 2 rows
    {
        int copy = (t >= 320);
        int tq   = t - copy * 320;
        if (tq < NQ) {
            float qx  = (float)((tq % QW) * QSKIP);
            float qy  = (float)((tq / QW) * QSKIP);
            float cy0 = qy - (float)(blk * 2);
            float cy1 = cy0 - 1.0f;                       // exact small ints
            float K0  = (0.81f * cy0) * cy0;
            float K1  = (0.81f * cy1) * cy1;
            unsigned char* h0 = &sB.cnt[((copy * 2 + 0) * NQ + tq) * RPAD];
            unsigned char* h1 = &sB.cnt[((copy * 2 + 1) * NQ + tq) * RPAD];
            const float4*       suA = sU4   + copy * 80;        // row 0
            const float4*       suB = sU4   + 160 + copy * 80;  // row 1
            const unsigned int* slA = sLab2 + copy * 80;
            const unsigned int* slB = sLab2 + 160 + copy * 80;
            float cx0 = qx - (float)(copy * 160);
            #pragma unroll 4
            for (int j = 0; j < 80; j++) {
                float4       uA = suA[j];                 // 2 independent
                float4       uB = suB[j];                 // LDS chains
                unsigned int lA = slA[j];
                unsigned int lB = slB[j];
                float cx1 = cx0 - 1.0f;
                float x00 = cx0 * cx0, x11 = cx1 * cx1;
                float rA0 = fmaf(x00, 0.81f, K0);
                float tA0 = fmaf(cx0, uA.x, fmaf(cy0, uA.y, -C1F));
                float rA1 = fmaf(x11, 0.81f, K0);
                float tA1 = fmaf(cx1, uA.z, fmaf(cy0, uA.w, -C1F));
                float rB0 = fmaf(x00, 0.81f, K1);
                float tB0 = fmaf(cx0, uB.x, fmaf(cy1, uB.y, -C1F));
                float rB1 = fmaf(x11, 0.81f, K1);
                float tB1 = fmaf(cx1, uB.z, fmaf(cy1, uB.w, -C1F));
                if (tA0 * fabsf(tA0) > rA0) h0[lA & 0xFFFFu] += 1;
                if (tA1 * fabsf(tA1) > rA1) h0[lA >> 16]     += 1;
                if (tB0 * fabsf(tB0) > rB0) h1[lB & 0xFFFFu] += 1;
                if (tB1 * fabsf(tB1) > rB1) h1[lB >> 16]     += 1;
                cx0 -= 2.0f;                              // exact small ints
            }
        }
    }
    __syncthreads();

    // ---------------- flush: widen u8->u16 lanes, merge 4 rows, 6 REDs/query -
    if (t < NQ) {
        const unsigned int* r0 =
            reinterpret_cast<const unsigned int*>(&sB.cnt[(0 * NQ + t) * RPAD]);
        const unsigned int* r1 =
            reinterpret_cast<const unsigned int*>(&sB.cnt[(1 * NQ + t) * RPAD]);
        const unsigned int* r2 =
            reinterpret_cast<const unsigned int*>(&sB.cnt[(2 * NQ + t) * RPAD]);
        const unsigned int* r3 =
            reinterpret_cast<const unsigned int*>(&sB.cnt[(3 * NQ + t) * RPAD]);
        #pragma unroll
        for (int g = 0; g < NG; g++) {
            unsigned int a = r0[g], b = r1[g], c = r2[g], d = r3[g];
            unsigned int lo = __byte_perm(a, 0, 0x4140) + __byte_perm(b, 0, 0x4140)
                            + __byte_perm(c, 0, 0x4140) + __byte_perm(d, 0, 0x4140);
            unsigned int hi = __byte_perm(a, 0, 0x4342) + __byte_perm(b, 0, 0x4342)
                            + __byte_perm(c, 0, 0x4342) + __byte_perm(d, 0, 0x4342);
            unsigned long long v = (unsigned long long)lo
                                 | ((unsigned long long)hi << 32);
            if (v) atomicAdd(&g_accP[t * NG + g], v);     // exact u16 lanes
        }
    }
    if (t < NC && sCC[t]) atomicAdd(&g_clsCnt[t], sCC[t]);

    // ---------------- software grid barrier (all 120 blocks co-resident) -----
    __threadfence();
    __syncthreads();
    if (t == 0) {
        atomicAdd(&g_phase1, 1);
        while (atomicAdd(&g_phase1, 0) < BLKS) __nanosleep(64);
    }
    __syncthreads();

    // ---------------- phase 2: stage table (overwrites histograms) -----------
    for (int i = t; i < NQ * NG; i += THR) sB.tab[i] = __ldcg(&g_accP[i]);
    __syncthreads();

    // per-class argmax on u16 lanes, integer compare (first-index ties)
    {
        int w = t >> 5;                       // 20 warps -> classes w, w+20
        for (int c = w; c < NC; c += 20) {
            int g  = c >> 2;
            int sh = (c & 3) * 16;
            int best = -1, bq = 0;
            for (int q = lane; q < NQ; q += 32) {
                int v = (int)((sB.tab[q * NG + g] >> sh) & 0xFFFFu);
                if (v > best) { best = v; bq = q; }
            }
            #pragma unroll
            for (int off = 16; off; off >>= 1) {
                int ov = __shfl_down_sync(0xffffffffu, best, off);
                int oq = __shfl_down_sync(0xffffffffu, bq,   off);
                if (ov > best || (ov == best && oq < bq)) { best = ov; bq = oq; }
            }
            if (lane == 0) { sBQ[c] = bq; sBV[c] = (float)best; }
        }
    }
    __syncthreads();

    // z-sum over this block's 640 pixels (data still hot in smem)
    {
        int lab = reinterpret_cast<unsigned short*>(sLab2)[t];
        if (lab > 0) {
            float2 u  = reinterpret_cast<float2*>(sU4)[t];
            int q     = sBQ[lab];
            int row   = (t >= WW);
            int col   = t - row * WW;
            float qx  = (float)((q % QW) * QSKIP);
            float qy  = (float)((q / QW) * QSKIP);
            float cx  = qx - (float)col;
            float cy  = qy - (float)(blk * 2 + row);
            if (itest(cx, cy, u.x, u.y))                  // same rounding as vote
                atomicAdd(&sZ[lab], sDz[t]);
        }
    }
    __syncthreads();
    if (t < NC && sZ[t] != 0.0f) atomicAdd(&g_zsum[t], sZ[t]);
    __threadfence();
    __syncthreads();
    if (t == 0) {
        int k = atomicAdd(&g_phase2, 1);
        if (k == BLKS - 1) sLast = 1;
    }
    __syncthreads();
    if (!sLast) return;

    // ================= last block: assemble output + reset scratch ===========
    if (t < NC) {
        __threadfence();     // acquire published g_zsum / g_clsCnt
        int c = t;
        float fx  = mdata[0] + EPSF;
        float fy  = mdata[4] + EPSF;
        float ppx = mdata[2];
        float ppy = mdata[5];

        float bv = sBV[c];
        int   bq = sBQ[c];
        float bx = (float)((bq % QW) * QSKIP);
        float by = (float)((bq / QW) * QSKIP);

        float cc = (float)__ldcg(&g_clsCnt[c]);
        float z  = __ldcg(&g_zsum[c]) / (bv + EPSF);  // cnt == best_votes

        float ex = extents[c * 3 + 0];
        float ey = extents[c * 3 + 1];
        float ez = extents[c * 3 + 2];
        float half = 0.5f * sqrtf(ex * ex + ey * ey + ez * ez);

        float zsafe = (fabsf(z) > EPSF) ? z : EPSF;
        float r = fx * half / zsafe;

        bool valid = (bv >= 50.0f) && (cc >= 500.0f) && (bv / (cc + EPSF) >= 0.02f);
        float score = valid ? bv : 0.0f;

        float* o = out + c * 14;
        o[0]  = 0.0f;
        o[1]  = (float)c;
        o[2]  = bx - r;
        o[3]  = by - r;
        o[4]  = bx + r;
        o[5]  = by + r;
        o[6]  = score;
        o[7]  = poses[c * 13 + 6];
        o[8]  = poses[c * 13 + 7];
        o[9]  = poses[c * 13 + 8];
        o[10] = poses[c * 13 + 9];
        o[11] = (bx - ppx) * z / fx;
        o[12] = (by - ppy) * z / fy;
        o[13] = z;

        // reset per-launch accumulators for the next graph replay
        g_clsCnt[c] = 0;
        g_zsum[c]   = 0.0f;
    }
    for (int i = t; i < NQ * NG; i += THR) g_accP[i] = 0ULL;
    __threadfence();
    if (t == 0) { g_phase1 = 0; g_phase2 = 0; }
}

// ---------------- launch ------------------------------------------------------
extern "C" void kernel_launch(void* const* d_in, const int* in_sizes, int n_in,
                              void* d_out, int out_size) {
    const int*   label   = (const int*)  d_in[0];   // (1,240,320) int32
    const float* vp      = (const float*)d_in[1];   // (1,66,240,320) f32
    const float* extents = (const float*)d_in[2];   // (22,3) f32
    const float* poses   = (const float*)d_in[3];   // (22,13) f32
    const float* mdata   = (const float*)d_in[4];   // (1,9) f32
    float*       out     = (float*)d_out;           // (1,22,14) f32

    k_all<<<BLKS, THR>>>(label, vp, extents, poses, mdata, out);
}

// round 8
// speedup vs baseline: 1.0474x; 1.0474x over previous
#include <cuda_runtime.h>
#include <cuda_bf16.h>

#define PP     76800     // H*W
#define HH     240
#define WW     320
#define NC     22        // classes
#define NR     7         // u64 per query row (28 u16 class lanes)
#define RW     28        // u16 lanes per histogram row (56B, 8B aligned)
#define NQ     300       // query points (15*20)
#define QW     20
#define QSKIP  16
#define EPSF   1e-6f
#define C1F    (0.9f * 1e-6f)

#define THR    640       // 2 copies of 300 query threads
#define BLKS   240       // 1 image row per block; <=2 blocks/SM => co-resident

// ---------------- device scratch (zero-init; reset by last block each launch) -
__device__ unsigned long long g_accP[NQ * NR];
__device__ int                g_clsCnt[NC];
__device__ float              g_zsum[NC];
__device__ int                g_phase1;
__device__ int                g_phase2;

// Inlier bit. rhs/t identical to prior rounds; compare via exact sign of
// RN(rhs - t*|t|)  ==  (t*|t| > rhs)  bit-for-bit (FADD sign is exact).
__device__ __forceinline__ unsigned ibit(float cx, float cy, float ux, float uy) {
    float rhs = fmaf(cx * cx, 0.81f, (0.81f * cy) * cy);
    float tv  = fmaf(cx, ux, fmaf(cy, uy, -C1F));
    float tt  = tv * fabsf(tv);
    return __float_as_uint(rhs - tt) >> 31;
}

// =============== single persistent kernel ====================================
__global__ void __launch_bounds__(THR, 2) k_all(const int* __restrict__ label,
                                                const float* __restrict__ vp,
                                                const float* __restrict__ extents,
                                                const float* __restrict__ poses,
                                                const float* __restrict__ mdata,
                                                float* __restrict__ out) {
    __shared__ union {
        unsigned short     hist[2 * NQ * RW];   // 33.6 KB vote histograms
        unsigned long long tab[NQ * NR];        // 16.8 KB staged vote table
    } sB;
    __shared__ float4        sP[WW];            // sorted (ux, uy, px, dz)
    __shared__ unsigned char sLabS[WW];         // sorted labels
    __shared__ int   sStart[NC + 2];            // class segment starts
    __shared__ int   sCur[NC];                  // scatter cursors
    __shared__ int   sCC[NC];
    __shared__ int   sBQ[NC];
    __shared__ float sBV[NC];
    __shared__ float sZ[NC];
    __shared__ int   sLast;

    int t    = threadIdx.x;
    int lane = t & 31;
    int row  = blockIdx.x;

    for (int i = t; i < NQ * RW; i += THR)        // zero hist (as u32 pairs)
        reinterpret_cast<unsigned int*>(sB.hist)[i] = 0u;
    if (t < NC) { sCC[t] = 0; sZ[t] = 0.0f; }
    if (t == 0) sLast = 0;
    __syncthreads();

    // ---------------- prep: one pixel per thread (t < 320) -------------------
    float ux = 0.0f, uy = 0.0f, dz = 0.0f;
    int   lab = 0;
    if (t < WW) {
        int p = row * WW + t;
        lab = label[p];
        if (lab > 0) {
            float dx = vp[(3 * lab + 0) * PP + p];
            float dy = vp[(3 * lab + 1) * PP + p];
            dz       = vp[(3 * lab + 2) * PP + p];
            float dn = sqrtf(dx * dx + dy * dy) + EPSF;
            ux = dx / dn;
            uy = dy / dn;
        }
        unsigned m = __match_any_sync(0xffffffffu, lab);
        if (lane == __ffs(m) - 1) atomicAdd(&sCC[lab], __popc(m));
    }
    __syncthreads();

    // class-offset scan (warp 0) -> segment starts + scatter cursors
    if (t < 32) {
        int v = (t < NC) ? sCC[t] : 0;
        int s = v;
        #pragma unroll
        for (int o = 1; o < 32; o <<= 1) {
            int u = __shfl_up_sync(0xffffffffu, s, o);
            if (lane >= o) s += u;
        }
        if (t < NC) { sStart[t + 1] = s; sCur[t] = s - v; }
        if (t == 0) sStart[0] = 0;
    }
    __syncthreads();

    // scatter: counting sort by label
    if (t < WW) {
        int pos = atomicAdd(&sCur[lab], 1);
        sP[pos]    = make_float4(ux, uy, (float)t, dz);
        sLabS[pos] = (unsigned char)lab;
    }
    __syncthreads();

    // ---------------- vote: sorted walk, register counter, no RMW ------------
    {
        int copy = (t >= 320) ? 1 : 0;
        int tq   = t - copy * 320;
        if (tq < NQ) {
            float qx = (float)((tq % QW) * QSKIP);
            float qy = (float)((tq / QW) * QSKIP);
            float cy = qy - (float)row;
            unsigned short* myC = &sB.hist[(copy * NQ + tq) * RW];
            int fg  = sStart[1];                 // bg pixels [0, fg) skipped
            int mid = (fg + WW) >> 1;
            int beg = copy ? mid : fg;
            int end = copy ? WW  : mid;
            if (beg < end) {
                int c = 1;
                while (sStart[c + 1] <= beg) c++;          // class containing beg
                int i = beg;
                unsigned cnt = 0;
                while (i < end) {
                    int nb = min(end, sStart[c + 1]);
                    for (; i < nb; i++) {                  // warp-uniform bounds
                        float4 pp = sP[i];                 // smem broadcast
                        float cx  = qx - pp.z;
                        cnt += ibit(cx, cy, pp.x, pp.y);   // register accumulate
                    }
                    myC[c] = (unsigned short)(myC[c] + cnt);  // rare flush
                    cnt = 0;
                    c++;
                    while (c < NC && sStart[c + 1] <= i) c++;
                }
            }
        }
    }
    __syncthreads();

    // ---------------- flush: merge 2 copies (u64 lane add, counts<=320) ------
    if (t < NQ) {
        const unsigned long long* r0 =
            reinterpret_cast<const unsigned long long*>(&sB.hist[t * RW]);
        const unsigned long long* r1 =
            reinterpret_cast<const unsigned long long*>(&sB.hist[(NQ + t) * RW]);
        #pragma unroll
        for (int k = 0; k < NR; k++) {
            unsigned long long v = r0[k] + r1[k];
            if (v) atomicAdd(&g_accP[t * NR + k], v);      // exact u16 lanes
        }
    }
    if (t < NC && sCC[t]) atomicAdd(&g_clsCnt[t], sCC[t]);

    // ---------------- grid barrier (all 240 blocks co-resident by occupancy) -
    __threadfence();
    __syncthreads();
    if (t == 0) {
        atomicAdd(&g_phase1, 1);
        while (atomicAdd(&g_phase1, 0) < BLKS) __nanosleep(64);
    }
    __syncthreads();

    // ---------------- phase 2: stage table (overwrites histograms) -----------
    for (int i = t; i < NQ * NR; i += THR) sB.tab[i] = __ldcg(&g_accP[i]);
    __syncthreads();

    // per-class argmax on u16 lanes, integer compare (first-index ties)
    {
        int w = t >> 5;                          // 20 warps
        for (int c = w; c < NC; c += 20) {
            int g  = c >> 2;
            int sh = (c & 3) * 16;
            int best = -1, bq = 0;
            for (int q = lane; q < NQ; q += 32) {
                int v = (int)((sB.tab[q * NR + g] >> sh) & 0xFFFFu);
                if (v > best) { best = v; bq = q; }
            }
            #pragma unroll
            for (int off = 16; off; off >>= 1) {
                int ov = __shfl_down_sync(0xffffffffu, best, off);
                int oq = __shfl_down_sync(0xffffffffu, bq,   off);
                if (ov > best || (ov == best && oq < bq)) { best = ov; bq = oq; }
            }
            if (lane == 0) { sBQ[c] = bq; sBV[c] = (float)best; }
        }
    }
    __syncthreads();

    // z-sum over this block's pixels (sorted arrays still hot in smem)
    if (t < WW) {
        int lb = sLabS[t];
        if (lb > 0) {
            float4 pp = sP[t];
            int q = sBQ[lb];
            float qx = (float)((q % QW) * QSKIP);
            float qy = (float)((q / QW) * QSKIP);
            float cy = qy - (float)row;
            float cx = qx - pp.z;
            if (ibit(cx, cy, pp.x, pp.y))        // same rounding as vote
                atomicAdd(&sZ[lb], pp.w);
        }
    }
    __syncthreads();
    if (t < NC && sZ[t] != 0.0f) atomicAdd(&g_zsum[t], sZ[t]);
    __threadfence();
    __syncthreads();
    if (t == 0) {
        if (atomicAdd(&g_phase2, 1) == BLKS - 1) sLast = 1;
    }
    __syncthreads();
    if (!sLast) return;

    // ================= last block: assemble output + reset scratch ===========
    if (t < NC) {
        int c = t;
        float fx  = mdata[0] + EPSF;
        float fy  = mdata[4] + EPSF;
        float ppx = mdata[2];
        float ppy = mdata[5];

        float bv = sBV[c];
        int   bq = sBQ[c];
        float bx = (float)((bq % QW) * QSKIP);
        float by = (float)((bq / QW) * QSKIP);

        float cc = (float)__ldcg(&g_clsCnt[c]);
        float z  = __ldcg(&g_zsum[c]) / (bv + EPSF);   // cnt == best_votes

        float ex = extents[c * 3 + 0];
        float ey = extents[c * 3 + 1];
        float ez = extents[c * 3 + 2];
        float half = 0.5f * sqrtf(ex * ex + ey * ey + ez * ez);

        float zsafe = (fabsf(z) > EPSF) ? z : EPSF;
        float r = fx * half / zsafe;

        bool valid = (bv >= 50.0f) && (cc >= 500.0f) && (bv / (cc + EPSF) >= 0.02f);
        float score = valid ? bv : 0.0f;

        float* o = out + c * 14;
        o[0]  = 0.0f;
        o[1]  = (float)c;
        o[2]  = bx - r;
        o[3]  = by - r;
        o[4]  = bx + r;
        o[5]  = by + r;
        o[6]  = score;
        o[7]  = poses[c * 13 + 6];
        o[8]  = poses[c * 13 + 7];
        o[9]  = poses[c * 13 + 8];
        o[10] = poses[c * 13 + 9];
        o[11] = (bx - ppx) * z / fx;
        o[12] = (by - ppy) * z / fy;
        o[13] = z;

        g_clsCnt[c] = 0;                 // reset for next graph replay
        g_zsum[c]   = 0.0f;
    }
    for (int i = t; i < NQ * NR; i += THR) g_accP[i] = 0ULL;
    __threadfence();
    if (t == 0) { g_phase1 = 0; g_phase2 = 0; }
}

// ---------------- launch ------------------------------------------------------
extern "C" void kernel_launch(void* const* d_in, const int* in_sizes, int n_in,
                              void* d_out, int out_size) {
    const int*   label   = (const int*)  d_in[0];   // (1,240,320) int32
    const float* vp      = (const float*)d_in[1];   // (1,66,240,320) f32
    const float* extents = (const float*)d_in[2];   // (22,3) f32
    const float* poses   = (const float*)d_in[3];   // (22,13) f32
    const float* mdata   = (const float*)d_in[4];   // (1,9) f32
    float*       out     = (float*)d_out;           // (1,22,14) f32

    k_all<<<BLKS, THR>>>(label, vp, extents, poses, mdata, out);
}

// round 9
// speedup vs baseline: 1.0645x; 1.0164x over previous
#include <cuda_runtime.h>
#include <cuda_bf16.h>

#define PP     76800     // H*W
#define HH     240
#define WW     320
#define NC     22        // classes
#define NR     7         // u64 per query row (28 u16 class lanes)
#define RW     28        // u16 lanes per histogram row
#define NQ     300       // query points (15*20)
#define QW     20
#define QSKIP  16
#define EPSF   1e-6f
#define C1F    (0.9f * 1e-6f)

#define THR    640       // 2 copies of 300 query threads
#define BLKS   240       // 1 image row per block; 2 blocks/SM => co-resident
#define PAIRS  200       // max pixel pairs after per-class pad-to-4

typedef unsigned long long ull;

// ---------------- device scratch (zero-init; reset by last block each launch) -
__device__ ull   g_accP[NQ * NR];
__device__ int   g_clsCnt[NC];
__device__ float g_zsum[NC];
__device__ int   g_phase1;
__device__ int   g_phase2;

// ---------------- packed f32x2 ops (two independent RN fp32 lanes) -----------
#define FMA2(d,a,b,c) asm("fma.rn.f32x2 %0,%1,%2,%3;" : "=l"(d) : "l"(a),"l"(b),"l"(c))
#define MUL2(d,a,b)   asm("mul.rn.f32x2 %0,%1,%2;"   : "=l"(d) : "l"(a),"l"(b))
#define ADD2(d,a,b)   asm("add.rn.f32x2 %0,%1,%2;"   : "=l"(d) : "l"(a),"l"(b))

__device__ __forceinline__ ull pk2(float x) {
    unsigned u = __float_as_uint(x);
    return (ull)u | ((ull)u << 32);
}

// Packed inlier test: 2 pixels per call. Per-lane op sequence is EXACTLY the
// scalar sequence in ibit() below (same RN roundings) -> identical vote bits.
__device__ __forceinline__ unsigned ptest2(ulonglong2 u, ull npx2, ull qx2,
                                           ull cy2, ull K2, ull mC1F2,
                                           ull c81_2, ull mOne2) {
    ull cx2, s2, rhs2, w2, t2, tt2, d2;
    ADD2(cx2, qx2, npx2);                        // cx = qx + (-px)
    MUL2(s2, cx2, cx2);
    FMA2(rhs2, s2, c81_2, K2);                   // rhs = cx^2*0.81 + K
    FMA2(w2, cy2, u.y, mC1F2);                   // w = cy*uy - C1F
    FMA2(t2, cx2, u.x, w2);                      // t = cx*ux + w
    ull ta2 = t2 & 0x7FFFFFFF7FFFFFFFULL;        // |t| per lane
    MUL2(tt2, t2, ta2);                          // tt = t*|t|
    FMA2(d2, tt2, mOne2, rhs2);                  // d = rhs - tt
    return (unsigned)((d2 >> 31) & 1ULL) + (unsigned)(d2 >> 63);  // sign bits
}

// Scalar twin (z-sum pass): identical rounding per op.
__device__ __forceinline__ unsigned ibit(float cx, float cy, float ux, float uy,
                                         float K) {
    float s   = cx * cx;
    float rhs = fmaf(s, 0.81f, K);
    float w   = fmaf(cy, uy, -C1F);
    float tv  = fmaf(cx, ux, w);
    float tt  = tv * fabsf(tv);
    float d   = fmaf(tt, -1.0f, rhs);
    return __float_as_uint(d) >> 31;
}

// =============== single persistent kernel ====================================
__global__ void __launch_bounds__(THR, 2) k_all(const int* __restrict__ label,
                                                const float* __restrict__ vp,
                                                const float* __restrict__ extents,
                                                const float* __restrict__ poses,
                                                const float* __restrict__ mdata,
                                                float* __restrict__ out) {
    __shared__ union {
        unsigned short hist[NQ * RW];       // 16.8 KB vote histogram (direct STS)
        ull            tab[NQ * NR];        // 16.8 KB staged vote table
    } sB;
    __shared__ ulonglong2    sUP[PAIRS];    // packed (ux0,ux1 | uy0,uy1)
    __shared__ ull           sNPX[PAIRS];   // packed (-px0, -px1)
    __shared__ float2        sZU[WW];       // original-order (ux,uy) for z-sum
    __shared__ float         sDz[WW];
    __shared__ unsigned char sLab[WW];
    __shared__ int   sPst[NC + 1];          // padded class segment starts [1..22]
    __shared__ int   sCur[NC];
    __shared__ int   sCC[NC];
    __shared__ int   sBQ[NC];
    __shared__ float sBV[NC];
    __shared__ float sZ[NC];
    __shared__ int   sLast;

    int t    = threadIdx.x;
    int lane = t & 31;
    int row  = blockIdx.x;

    // zero histogram + packed pixel arrays (pads must be 0 => never vote)
    for (int i = t; i < NQ * RW / 2; i += THR)
        reinterpret_cast<unsigned int*>(sB.hist)[i] = 0u;
    for (int i = t; i < PAIRS * 4; i += THR)
        reinterpret_cast<unsigned int*>(sUP)[i] = 0u;
    for (int i = t; i < PAIRS * 2; i += THR)
        reinterpret_cast<unsigned int*>(sNPX)[i] = 0u;
    if (t < NC) { sCC[t] = 0; sZ[t] = 0.0f; }
    if (t == 0) sLast = 0;
    __syncthreads();

    // ---------------- prep: one pixel per thread (t < 320) -------------------
    float ux = 0.0f, uy = 0.0f, dz = 0.0f;
    int   lab = 0;
    if (t < WW) {
        int p = row * WW + t;
        lab = label[p];
        if (lab > 0) {
            float dx = vp[(3 * lab + 0) * PP + p];
            float dy = vp[(3 * lab + 1) * PP + p];
            dz       = vp[(3 * lab + 2) * PP + p];
            float dn = sqrtf(dx * dx + dy * dy) + EPSF;
            ux = dx / dn;
            uy = dy / dn;
        }
        sZU[t]  = make_float2(ux, uy);
        sDz[t]  = dz;
        sLab[t] = (unsigned char)lab;
        unsigned m = __match_any_sync(0xffffffffu, lab);
        if (lane == __ffs(m) - 1) atomicAdd(&sCC[lab], __popc(m));
    }
    __syncthreads();

    // padded segment starts (warp 0): class c=lane+1, count padded to x4
    if (t < 32) {
        int c = t + 1;
        int v = (t < 21) ? ((sCC[c] + 3) & ~3) : 0;
        int s = v;
        #pragma unroll
        for (int o = 1; o < 32; o <<= 1) {
            int u = __shfl_up_sync(0xffffffffu, s, o);
            if (lane >= o) s += u;
        }
        if (t < 21) {
            int excl = s - v;
            sPst[c]  = excl;
            sCur[c]  = excl;
            if (t == 20) sPst[22] = s;
        }
    }
    __syncthreads();

    // scatter fg pixels into padded, class-sorted packed arrays
    if (t < WW && lab > 0) {
        int pos  = atomicAdd(&sCur[lab], 1);
        int pair = pos >> 1, sub = pos & 1;
        float* uP = reinterpret_cast<float*>(sUP);
        uP[pair * 4 + sub]     = ux;
        uP[pair * 4 + 2 + sub] = uy;
        reinterpret_cast<float*>(sNPX)[pos] = -(float)t;
    }
    __syncthreads();

    // ---------------- vote: packed f32x2, direct-store histogram -------------
    {
        int c0 = 0, tq = -1;
        if (t < NQ)                    { tq = t;        c0 = 1; }  // odd classes
        else if (t >= 320 && t < 620)  { tq = t - 320;  c0 = 2; }  // even classes
        if (tq >= 0) {
            float qx = (float)((tq % QW) * QSKIP);
            float qy = (float)((tq / QW) * QSKIP);
            float cy = qy - (float)row;
            float K  = (0.81f * cy) * cy;
            ull qx2    = pk2(qx);
            ull cy2    = pk2(cy);
            ull K2     = pk2(K);
            ull mC1F2  = pk2(-C1F);
            ull c81_2  = pk2(0.81f);
            ull mOne2  = pk2(-1.0f);
            unsigned short* myC = &sB.hist[tq * RW];
            for (int c = c0; c <= 21; c += 2) {
                int pb = sPst[c] >> 1;
                int pe = sPst[c + 1] >> 1;        // multiple of 2 pairs
                unsigned cnt = 0;
                for (int i = pb; i < pe; i += 2) {
                    ulonglong2 ua = sUP[i];
                    ull        na = sNPX[i];
                    ulonglong2 ub = sUP[i + 1];
                    ull        nb = sNPX[i + 1];
                    cnt += ptest2(ua, na, qx2, cy2, K2, mC1F2, c81_2, mOne2);
                    cnt += ptest2(ub, nb, qx2, cy2, K2, mC1F2, c81_2, mOne2);
                }
                myC[c] = (unsigned short)cnt;     // direct store (disjoint lanes)
            }
        }
    }
    __syncthreads();

    // ---------------- flush: 7 u64 REDs per query ----------------------------
    if (t < NQ) {
        const ull* r0 = reinterpret_cast<const ull*>(&sB.hist[t * RW]);
        #pragma unroll
        for (int k = 0; k < NR; k++) {
            ull v = r0[k];
            if (v) atomicAdd(&g_accP[t * NR + k], v);   // exact u16 lanes
        }
    }
    if (t < NC && sCC[t]) atomicAdd(&g_clsCnt[t], sCC[t]);

    // ---------------- grid barrier (240 blocks co-resident at 2/SM) ----------
    __threadfence();
    __syncthreads();
    if (t == 0) {
        atomicAdd(&g_phase1, 1);
        while (atomicAdd(&g_phase1, 0) < BLKS) __nanosleep(64);
    }
    __syncthreads();

    // ---------------- phase 2: stage table (overwrites histogram) ------------
    for (int i = t; i < NQ * NR; i += THR) sB.tab[i] = __ldcg(&g_accP[i]);
    __syncthreads();

    // per-class argmax on u16 lanes, integer compare (first-index ties)
    {
        int w = t >> 5;                          // 20 warps
        for (int c = w; c < NC; c += 20) {
            int g  = c >> 2;
            int sh = (c & 3) * 16;
            int best = -1, bq = 0;
            for (int q = lane; q < NQ; q += 32) {
                int v = (int)((sB.tab[q * NR + g] >> sh) & 0xFFFFu);
                if (v > best) { best = v; bq = q; }
            }
            #pragma unroll
            for (int off = 16; off; off >>= 1) {
                int ov = __shfl_down_sync(0xffffffffu, best, off);
                int oq = __shfl_down_sync(0xffffffffu, bq,   off);
                if (ov > best || (ov == best && oq < bq)) { best = ov; bq = oq; }
            }
            if (lane == 0) { sBQ[c] = bq; sBV[c] = (float)best; }
        }
    }
    __syncthreads();

    // z-sum over this block's pixels (scalar twin of the packed test)
    if (t < WW) {
        int lb = sLab[t];
        if (lb > 0) {
            float2 u = sZU[t];
            int q = sBQ[lb];
            float qx = (float)((q % QW) * QSKIP);
            float qy = (float)((q / QW) * QSKIP);
            float cy = qy - (float)row;
            float K  = (0.81f * cy) * cy;
            float cx = qx - (float)t;
            if (ibit(cx, cy, u.x, u.y, K))
                atomicAdd(&sZ[lb], sDz[t]);
        }
    }
    __syncthreads();
    if (t < NC && sZ[t] != 0.0f) atomicAdd(&g_zsum[t], sZ[t]);
    __threadfence();
    __syncthreads();
    if (t == 0) {
        if (atomicAdd(&g_phase2, 1) == BLKS - 1) sLast = 1;
    }
    __syncthreads();
    if (!sLast) return;

    // ================= last block: assemble output + reset scratch ===========
    if (t < NC) {
        int c = t;
        float fx  = mdata[0] + EPSF;
        float fy  = mdata[4] + EPSF;
        float ppx = mdata[2];
        float ppy = mdata[5];

        float bv = sBV[c];
        int   bq = sBQ[c];
        float bx = (float)((bq % QW) * QSKIP);
        float by = (float)((bq / QW) * QSKIP);

        float cc = (float)__ldcg(&g_clsCnt[c]);
        float z  = __ldcg(&g_zsum[c]) / (bv + EPSF);   // cnt == best_votes

        float ex = extents[c * 3 + 0];
        float ey = extents[c * 3 + 1];
        float ez = extents[c * 3 + 2];
        float half = 0.5f * sqrtf(ex * ex + ey * ey + ez * ez);

        float zsafe = (fabsf(z) > EPSF) ? z : EPSF;
        float r = fx * half / zsafe;

        bool valid = (bv >= 50.0f) && (cc >= 500.0f) && (bv / (cc + EPSF) >= 0.02f);
        float score = valid ? bv : 0.0f;

        float* o = out + c * 14;
        o[0]  = 0.0f;
        o[1]  = (float)c;
        o[2]  = bx - r;
        o[3]  = by - r;
        o[4]  = bx + r;
        o[5]  = by + r;
        o[6]  = score;
        o[7]  = poses[c * 13 + 6];
        o[8]  = poses[c * 13 + 7];
        o[9]  = poses[c * 13 + 8];
        o[10] = poses[c * 13 + 9];
        o[11] = (bx - ppx) * z / fx;
        o[12] = (by - ppy) * z / fy;
        o[13] = z;

        g_clsCnt[c] = 0;                 // reset for next graph replay
        g_zsum[c]   = 0.0f;
    }
    for (int i = t; i < NQ * NR; i += THR) g_accP[i] = 0ULL;
    __threadfence();
    if (t == 0) { g_phase1 = 0; g_phase2 = 0; }
}

// ---------------- launch ------------------------------------------------------
extern "C" void kernel_launch(void* const* d_in, const int* in_sizes, int n_in,
                              void* d_out, int out_size) {
    const int*   label   = (const int*)  d_in[0];   // (1,240,320) int32
    const float* vp      = (const float*)d_in[1];   // (1,66,240,320) f32
    const float* extents = (const float*)d_in[2];   // (22,3) f32
    const float* poses   = (const float*)d_in[3];   // (22,13) f32
    const float* mdata   = (const float*)d_in[4];   // (1,9) f32
    float*       out     = (float*)d_out;           // (1,22,14) f32

    k_all<<<BLKS, THR>>>(label, vp, extents, poses, mdata, out);
}